// round 15
// baseline (speedup 1.0000x reference)
#include <cuda_runtime.h>
#include <cuda_bf16.h>

// BilateralBlur v10: v7 + one-step load prefetch (double-buffered main loads),
// delay line replaced by L1-hit reloads through the output pointer.
// 2 px/thread, 32-row chunks, parked-pointer branch-free loads, 1024-CTA
// single wave @ 7 CTAs/SM.

#define LOG2E 1.4426950408889634f
#define FULLM 0xffffffffu

__device__ __forceinline__ float ex2a(float x){ float r; asm("ex2.approx.ftz.f32 %0, %1;" : "=f"(r) : "f"(x)); return r; }
__device__ __forceinline__ float lg2a(float x){ float r; asm("lg2.approx.ftz.f32 %0, %1;" : "=f"(r) : "f"(x)); return r; }
__device__ __forceinline__ float rcpa(float x){ float r; asm("rcp.approx.ftz.f32 %0, %1;" : "=f"(r) : "f"(x)); return r; }
__device__ __forceinline__ float2 z2(){ return make_float2(0.f, 0.f); }

struct Slot { float2 z, hb, hd; };

__global__ __launch_bounds__(128, 7)
void bilateral_blur_v10(const float* __restrict__ bright,
                        const float* __restrict__ dark,
                        const float* __restrict__ depths,
                        const float* __restrict__ p_dv,
                        const float* __restrict__ p_sv,
                        const float* __restrict__ p_dexp,
                        const float* __restrict__ p_deps,
                        const float* __restrict__ p_ce,
                        float* __restrict__ out,
                        int H, int W)
{
    const int lane = threadIdx.x & 31;
    const int warp = threadIdx.x >> 5;
    const int xs = blockIdx.x * 64;                 // strip start column
    const int x  = xs + 2 * lane;                   // this thread's 2 columns (even)
    const int ys = (blockIdx.y * 4 + warp) * 32;    // 32-row chunk start
    const size_t base = (size_t)blockIdx.z * (size_t)H * (size_t)W;

    const float inv2dv = 0.5f / *p_dv;
    const float inv2sv = 0.5f / *p_sv;
    const float dexp = *p_dexp;
    const float deps = *p_deps;
    const float ce   = *p_ce;
    const float K2   = -inv2dv * LOG2E;             // w = ex2(t^2*K2 + lsw)
    const float lswB = -inv2sv * LOG2E;             // |offset| = 1
    const float lswA = -4.0f * inv2sv * LOG2E;      // |offset| = 2

    // halo: lane0 loads left pair (x-2,x-1), lane31 loads right pair (x+2,x+3)
    const bool haloL = (xs > 0);
    const bool haloR = (xs + 64 < W);
    const bool hv = (lane == 0) ? haloL : ((lane == 31) ? haloR : false);
    const ptrdiff_t ho = (lane == 0) ? (ptrdiff_t)-2 : (ptrdiff_t)2;

    int y = ys - 2;
    const int ylim = (ys + 34 < H) ? (ys + 34) : H;  // rows ys-2 .. ys+33 consumed
    const int yc0  = (y < 0) ? 0 : y;                // parked start row (fault-safe)

    const float* pb = bright + base + (ptrdiff_t)yc0 * W + x;
    const float* pd = dark   + base + (ptrdiff_t)yc0 * W + x;
    const float* pz = depths + base + (ptrdiff_t)yc0 * W + x;
    float*       po = out    + base + (ptrdiff_t)ys  * W + x;

    // uniform (loop-invariant) offsets: epilogue reloads original bright/dark
    // of the output row straight through po -> guaranteed L1 hits.
    const ptrdiff_t o2b = bright - out;
    const ptrdiff_t o2d = dark - out;

    Slot s0, s1, s2, s3, s4;
    s0.z = s1.z = s2.z = s3.z = s4.z = z2();
    s0.hb = s1.hb = s2.hb = s3.hb = s4.hb = z2();
    s0.hd = s1.hd = s2.hd = s3.hd = s4.hd = z2();

    // prologue prefetch: row ys-2 (parked)
    float2 bn = __ldg((const float2*)pb);
    float2 dn = __ldg((const float2*)pd);
    float2 zn = __ldg((const float2*)pz);

#define HTAP(ZV, BV, DV, ZI, LSW, WS, BS, DS) \
    { float t = fmaf(ZV, ZI, -1.f); float w = ex2a(fmaf(t * t, K2, LSW)); \
      WS += w; BS = fmaf(BV, w, BS); DS = fmaf(DV, w, DS); }

#define VTAP(S, LSW) \
    { float t = fmaf((S).z.x, i0, -1.f); float w = ex2a(fmaf(t * t, K2, LSW)); \
      ws0 += w; bs0 = fmaf((S).hb.x, w, bs0); ds0 = fmaf((S).hd.x, w, ds0); } \
    { float t = fmaf((S).z.y, i1, -1.f); float w = ex2a(fmaf(t * t, K2, LSW)); \
      ws1 += w; bs1 = fmaf((S).hb.y, w, bs1); ds1 = fmaf((S).hd.y, w, ds1); }

#define STEP(S0, S1, S2, S3, S4) do { \
    /* 1. consume prefetched row y */ \
    float2 b = bn, d = dn, z = zn; \
    /* 2. halo for row y (pointers still at row y) */ \
    float2 eb = z2(), ed = z2(), ez = z2(); \
    if (hv) { \
        eb = __ldg((const float2*)(pb + ho)); \
        ed = __ldg((const float2*)(pd + ho)); \
        ez = __ldg((const float2*)(pz + ho)); \
    } \
    const bool valid = ((unsigned)y < (unsigned)ylim); \
    /* 3. advance (parked) and prefetch row y+1 */ \
    { ptrdiff_t adv = ((unsigned)y < (unsigned)(H - 1)) ? (ptrdiff_t)W : 0; \
      pb += adv; pd += adv; pz += adv; } \
    bn = __ldg((const float2*)pb); \
    dn = __ldg((const float2*)pd); \
    zn = __ldg((const float2*)pz); \
    /* 4. h-pass row y */ \
    float Lbx = __shfl_up_sync(FULLM, b.x, 1),   Lby = __shfl_up_sync(FULLM, b.y, 1); \
    float Ldx = __shfl_up_sync(FULLM, d.x, 1),   Ldy = __shfl_up_sync(FULLM, d.y, 1); \
    float Lzx = __shfl_up_sync(FULLM, z.x, 1),   Lzy = __shfl_up_sync(FULLM, z.y, 1); \
    float Rbx = __shfl_down_sync(FULLM, b.x, 1), Rby = __shfl_down_sync(FULLM, b.y, 1); \
    float Rdx = __shfl_down_sync(FULLM, d.x, 1), Rdy = __shfl_down_sync(FULLM, d.y, 1); \
    float Rzx = __shfl_down_sync(FULLM, z.x, 1), Rzy = __shfl_down_sync(FULLM, z.y, 1); \
    if (lane == 0)  { Lbx = eb.x; Lby = eb.y; Ldx = ed.x; Ldy = ed.y; Lzx = ez.x; Lzy = ez.y; } \
    if (lane == 31) { Rbx = eb.x; Rby = eb.y; Rdx = ed.x; Rdy = ed.y; Rzx = ez.x; Rzy = ez.y; } \
    float zix = rcpa(z.x), ziy = rcpa(z.y); \
    float ws0 = 1.f, bs0 = b.x, ds0 = d.x;   /* center tap w=1 */ \
    HTAP(Lzx, Lbx, Ldx, zix, lswA, ws0, bs0, ds0) \
    HTAP(Lzy, Lby, Ldy, zix, lswB, ws0, bs0, ds0) \
    HTAP(z.y, b.y, d.y, zix, lswB, ws0, bs0, ds0) \
    HTAP(Rzx, Rbx, Rdx, zix, lswA, ws0, bs0, ds0) \
    float ws1 = 1.f, bs1 = b.y, ds1 = d.y; \
    HTAP(Lzy, Lby, Ldy, ziy, lswA, ws1, bs1, ds1) \
    HTAP(z.x, b.x, d.x, ziy, lswB, ws1, bs1, ds1) \
    HTAP(Rzx, Rbx, Rdx, ziy, lswB, ws1, bs1, ds1) \
    HTAP(Rzy, Rby, Rdy, ziy, lswA, ws1, bs1, ds1) \
    float nh0 = rcpa(ws0), nh1 = rcpa(ws1); \
    /* 5. ring write; zero-pad OOB rows via selects (no branch) */ \
    S4.z.x  = valid ? z.x : 0.f;        S4.z.y  = valid ? z.y : 0.f; \
    S4.hb.x = valid ? bs0 * nh0 : 0.f;  S4.hb.y = valid ? bs1 * nh1 : 0.f; \
    S4.hd.x = valid ? ds0 * nh0 : 0.f;  S4.hd.y = valid ? ds1 * nh1 : 0.f; \
    /* 6. output row y-2 (center slot S2); center b/d reloaded via po (L1 hit) */ \
    if ((unsigned)(y - ys - 2) < 32u) { \
        float2 bc = __ldg((const float2*)(po + o2b)); \
        float2 dc = __ldg((const float2*)(po + o2d)); \
        float i0 = rcpa(S2.z.x), i1 = rcpa(S2.z.y); \
        float ws0 = 1.f, bs0 = S2.hb.x, ds0 = S2.hd.x; \
        float ws1 = 1.f, bs1 = S2.hb.y, ds1 = S2.hd.y; \
        VTAP(S0, lswA) VTAP(S1, lswB) VTAP(S3, lswB) VTAP(S4, lswA) \
        float n0 = rcpa(ws0), n1 = rcpa(ws1); \
        float bm0 = bs0 * n0, dm0 = ds0 * n0; \
        float bm1 = bs1 * n1, dm1 = ds1 * n1; \
        /* custom_pow(a,e) = ex2(e * lg2(max(|a|,1e-8))) */ \
        float devb0 = ex2a(dexp * lg2a(fmaxf(fabsf(bc.x - bm0), 1e-8f))) * ce; \
        float devd0 = fmaxf(ex2a(dexp * lg2a(fmaxf(fabsf(dc.x - dm0), 1e-8f))), deps); \
        float o0 = (devd0 * bc.x + devb0 * dc.x) * rcpa(devb0 + devd0); \
        float devb1 = ex2a(dexp * lg2a(fmaxf(fabsf(bc.y - bm1), 1e-8f))) * ce; \
        float devd1 = fmaxf(ex2a(dexp * lg2a(fmaxf(fabsf(dc.y - dm1), 1e-8f))), deps); \
        float o1 = (devd1 * bc.y + devb1 * dc.y) * rcpa(devb1 + devd1); \
        *(float2*)po = make_float2(o0, o1); \
        po += W; \
    } \
    y++; \
} while (0)

    // 36 steps: rows ys-2 .. ys+33 (OOB rows zeroed by selects; outputs ys..ys+31)
    #pragma unroll 1
    for (int it = 0; it < 7; ++it) {
        STEP(s1, s2, s3, s4, s0);
        STEP(s2, s3, s4, s0, s1);
        STEP(s3, s4, s0, s1, s2);
        STEP(s4, s0, s1, s2, s3);
        STEP(s0, s1, s2, s3, s4);
    }
    STEP(s1, s2, s3, s4, s0);   // step 36
#undef STEP
#undef HTAP
#undef VTAP
}

extern "C" void kernel_launch(void* const* d_in, const int* in_sizes, int n_in,
                              void* d_out, int out_size)
{
    const float* bright = (const float*)d_in[0];
    const float* dark   = (const float*)d_in[1];
    const float* depths = (const float*)d_in[2];
    const float* dv     = (const float*)d_in[3];
    const float* sv     = (const float*)d_in[4];
    const float* dexp   = (const float*)d_in[5];
    const float* deps   = (const float*)d_in[6];
    const float* ce     = (const float*)d_in[7];
    float* out = (float*)d_out;

    const int H = 1024, W = 1024;
    const int B = in_sizes[0] / (H * W);

    dim3 block(128, 1, 1);
    dim3 grid(W / 64, (H / 32) / 4, B);   // 16 x 8 x B = 1024 CTAs = one full wave @7/SM
    bilateral_blur_v10<<<grid, block>>>(bright, dark, depths,
                                        dv, sv, dexp, deps, ce,
                                        out, H, W);
}

// round 17
// speedup vs baseline: 1.0050x; 1.0050x over previous
#include <cuda_runtime.h>
#include <cuda_bf16.h>

// BilateralBlur v11: v7 with an 8-register diet -> 8 CTAs/SM (32 warps) to
// feed the MUFU pipe (measured ~70% busy in v7). The bC/dC delay line is
// replaced by epilogue reloads of the center row's bright/dark through the
// output pointer (thread-invariant offsets -> uniform regs; L1 hits).
// Structure otherwise identical to v7 (the 49.3us kernel).

#define LOG2E 1.4426950408889634f
#define FULLM 0xffffffffu

__device__ __forceinline__ float ex2a(float x){ float r; asm("ex2.approx.ftz.f32 %0, %1;" : "=f"(r) : "f"(x)); return r; }
__device__ __forceinline__ float lg2a(float x){ float r; asm("lg2.approx.ftz.f32 %0, %1;" : "=f"(r) : "f"(x)); return r; }
__device__ __forceinline__ float rcpa(float x){ float r; asm("rcp.approx.ftz.f32 %0, %1;" : "=f"(r) : "f"(x)); return r; }
__device__ __forceinline__ float2 z2(){ return make_float2(0.f, 0.f); }

struct Slot { float2 z, hb, hd; };

__global__ __launch_bounds__(128, 8)
void bilateral_blur_v11(const float* __restrict__ bright,
                        const float* __restrict__ dark,
                        const float* __restrict__ depths,
                        const float* __restrict__ p_dv,
                        const float* __restrict__ p_sv,
                        const float* __restrict__ p_dexp,
                        const float* __restrict__ p_deps,
                        const float* __restrict__ p_ce,
                        float* __restrict__ out,
                        int H, int W)
{
    const int lane = threadIdx.x & 31;
    const int warp = threadIdx.x >> 5;
    const int xs = blockIdx.x * 64;                 // strip start column
    const int x  = xs + 2 * lane;                   // this thread's 2 columns (even)
    const int ys = (blockIdx.y * 4 + warp) * 32;    // 32-row chunk start
    const size_t base = (size_t)blockIdx.z * (size_t)H * (size_t)W;

    const float inv2dv = 0.5f / *p_dv;
    const float inv2sv = 0.5f / *p_sv;
    const float dexp = *p_dexp;
    const float deps = *p_deps;
    const float ce   = *p_ce;
    const float K2   = -inv2dv * LOG2E;             // w = ex2(t^2*K2 + lsw)
    const float lswB = -inv2sv * LOG2E;             // |offset| = 1
    const float lswA = -4.0f * inv2sv * LOG2E;      // |offset| = 2

    // halo: lane0 loads left pair (x-2,x-1), lane31 loads right pair (x+2,x+3)
    const bool haloL = (xs > 0);
    const bool haloR = (xs + 64 < W);
    const bool hv = (lane == 0) ? haloL : ((lane == 31) ? haloR : false);
    const ptrdiff_t ho = (lane == 0) ? (ptrdiff_t)-2 : (ptrdiff_t)2;

    int y = ys - 2;
    const int ylim = (ys + 34 < H) ? (ys + 34) : H;  // rows ys-2 .. ys+33 consumed
    const int yc0  = (y < 0) ? 0 : y;                // parked start row (fault-safe)

    const float* pb = bright + base + (ptrdiff_t)yc0 * W + x;
    const float* pd = dark   + base + (ptrdiff_t)yc0 * W + x;
    const float* pz = depths + base + (ptrdiff_t)yc0 * W + x;
    float*       po = out    + base + (ptrdiff_t)ys  * W + x;

    // thread-invariant offsets (uniform datapath): epilogue reloads the
    // output row's original bright/dark through po -> L1 hits, no GPR cost.
    const ptrdiff_t o2b = bright - out;
    const ptrdiff_t o2d = dark - out;

    Slot s0, s1, s2, s3, s4;
    s0.z = s1.z = s2.z = s3.z = s4.z = z2();
    s0.hb = s1.hb = s2.hb = s3.hb = s4.hb = z2();
    s0.hd = s1.hd = s2.hd = s3.hd = s4.hd = z2();

#define HTAP(ZV, BV, DV, ZI, LSW, WS, BS, DS) \
    { float t = fmaf(ZV, ZI, -1.f); float w = ex2a(fmaf(t * t, K2, LSW)); \
      WS += w; BS = fmaf(BV, w, BS); DS = fmaf(DV, w, DS); }

#define VTAP(S, LSW) \
    { float t = fmaf((S).z.x, i0, -1.f); float w = ex2a(fmaf(t * t, K2, LSW)); \
      ws0 += w; bs0 = fmaf((S).hb.x, w, bs0); ds0 = fmaf((S).hd.x, w, ds0); } \
    { float t = fmaf((S).z.y, i1, -1.f); float w = ex2a(fmaf(t * t, K2, LSW)); \
      ws1 += w; bs1 = fmaf((S).hb.y, w, bs1); ds1 = fmaf((S).hd.y, w, ds1); }

#define STEP(S0, S1, S2, S3, S4) do { \
    /* unconditional loads from parked pointers (hoistable, fault-safe) */ \
    float2 b = __ldg((const float2*)pb); \
    float2 d = __ldg((const float2*)pd); \
    float2 z = __ldg((const float2*)pz); \
    float2 eb = z2(), ed = z2(), ez = z2(); \
    if (hv) { \
        eb = __ldg((const float2*)(pb + ho)); \
        ed = __ldg((const float2*)(pd + ho)); \
        ez = __ldg((const float2*)(pz + ho)); \
    } \
    const bool valid = ((unsigned)y < (unsigned)ylim); \
    { ptrdiff_t adv = ((unsigned)y < (unsigned)(H - 1)) ? (ptrdiff_t)W : 0; \
      pb += adv; pd += adv; pz += adv; } \
    float Lbx = __shfl_up_sync(FULLM, b.x, 1),   Lby = __shfl_up_sync(FULLM, b.y, 1); \
    float Ldx = __shfl_up_sync(FULLM, d.x, 1),   Ldy = __shfl_up_sync(FULLM, d.y, 1); \
    float Lzx = __shfl_up_sync(FULLM, z.x, 1),   Lzy = __shfl_up_sync(FULLM, z.y, 1); \
    float Rbx = __shfl_down_sync(FULLM, b.x, 1), Rby = __shfl_down_sync(FULLM, b.y, 1); \
    float Rdx = __shfl_down_sync(FULLM, d.x, 1), Rdy = __shfl_down_sync(FULLM, d.y, 1); \
    float Rzx = __shfl_down_sync(FULLM, z.x, 1), Rzy = __shfl_down_sync(FULLM, z.y, 1); \
    if (lane == 0)  { Lbx = eb.x; Lby = eb.y; Ldx = ed.x; Ldy = ed.y; Lzx = ez.x; Lzy = ez.y; } \
    if (lane == 31) { Rbx = eb.x; Rby = eb.y; Rdx = ed.x; Rdy = ed.y; Rzx = ez.x; Rzy = ez.y; } \
    float zix = rcpa(z.x), ziy = rcpa(z.y); \
    /* px0: center w=1 folded into init */ \
    float ws0 = 1.f, bs0 = b.x, ds0 = d.x; \
    HTAP(Lzx, Lbx, Ldx, zix, lswA, ws0, bs0, ds0) \
    HTAP(Lzy, Lby, Ldy, zix, lswB, ws0, bs0, ds0) \
    HTAP(z.y, b.y, d.y, zix, lswB, ws0, bs0, ds0) \
    HTAP(Rzx, Rbx, Rdx, zix, lswA, ws0, bs0, ds0) \
    /* px1 */ \
    float ws1 = 1.f, bs1 = b.y, ds1 = d.y; \
    HTAP(Lzy, Lby, Ldy, ziy, lswA, ws1, bs1, ds1) \
    HTAP(z.x, b.x, d.x, ziy, lswB, ws1, bs1, ds1) \
    HTAP(Rzx, Rbx, Rdx, ziy, lswB, ws1, bs1, ds1) \
    HTAP(Rzy, Rby, Rdy, ziy, lswA, ws1, bs1, ds1) \
    float nh0 = rcpa(ws0), nh1 = rcpa(ws1); \
    /* ring write: zero-pad semantics for OOB rows via selects (no branch) */ \
    S4.z.x  = valid ? z.x : 0.f;        S4.z.y  = valid ? z.y : 0.f; \
    S4.hb.x = valid ? bs0 * nh0 : 0.f;  S4.hb.y = valid ? bs1 * nh1 : 0.f; \
    S4.hd.x = valid ? ds0 * nh0 : 0.f;  S4.hd.y = valid ? ds1 * nh1 : 0.f; \
    if ((unsigned)(y - ys - 2) < 32u) {   /* output row y-2, center slot S2 */ \
        float2 bc = __ldg((const float2*)(po + o2b));   /* L1 hit */ \
        float2 dc = __ldg((const float2*)(po + o2d));   /* L1 hit */ \
        float i0 = rcpa(S2.z.x), i1 = rcpa(S2.z.y); \
        float ws0 = 1.f, bs0 = S2.hb.x, ds0 = S2.hd.x; \
        float ws1 = 1.f, bs1 = S2.hb.y, ds1 = S2.hd.y; \
        VTAP(S0, lswA) VTAP(S1, lswB) VTAP(S3, lswB) VTAP(S4, lswA) \
        float n0 = rcpa(ws0), n1 = rcpa(ws1); \
        float bm0 = bs0 * n0, dm0 = ds0 * n0; \
        float bm1 = bs1 * n1, dm1 = ds1 * n1; \
        /* custom_pow(a,e) = ex2(e * lg2(max(|a|,1e-8))) */ \
        float devb0 = ex2a(dexp * lg2a(fmaxf(fabsf(bc.x - bm0), 1e-8f))) * ce; \
        float devd0 = fmaxf(ex2a(dexp * lg2a(fmaxf(fabsf(dc.x - dm0), 1e-8f))), deps); \
        float o0 = (devd0 * bc.x + devb0 * dc.x) * rcpa(devb0 + devd0); \
        float devb1 = ex2a(dexp * lg2a(fmaxf(fabsf(bc.y - bm1), 1e-8f))) * ce; \
        float devd1 = fmaxf(ex2a(dexp * lg2a(fmaxf(fabsf(dc.y - dm1), 1e-8f))), deps); \
        float o1 = (devd1 * bc.y + devb1 * dc.y) * rcpa(devb1 + devd1); \
        *(float2*)po = make_float2(o0, o1); \
        po += W; \
    } \
    y++; \
} while (0)

    // 36 steps: rows ys-2 .. ys+33 (OOB rows zeroed by selects; outputs ys..ys+31)
    #pragma unroll 1
    for (int it = 0; it < 7; ++it) {
        STEP(s1, s2, s3, s4, s0);
        STEP(s2, s3, s4, s0, s1);
        STEP(s3, s4, s0, s1, s2);
        STEP(s4, s0, s1, s2, s3);
        STEP(s0, s1, s2, s3, s4);
    }
    STEP(s1, s2, s3, s4, s0);   // step 36
#undef STEP
#undef HTAP
#undef VTAP
}

extern "C" void kernel_launch(void* const* d_in, const int* in_sizes, int n_in,
                              void* d_out, int out_size)
{
    const float* bright = (const float*)d_in[0];
    const float* dark   = (const float*)d_in[1];
    const float* depths = (const float*)d_in[2];
    const float* dv     = (const float*)d_in[3];
    const float* sv     = (const float*)d_in[4];
    const float* dexp   = (const float*)d_in[5];
    const float* deps   = (const float*)d_in[6];
    const float* ce     = (const float*)d_in[7];
    float* out = (float*)d_out;

    const int H = 1024, W = 1024;
    const int B = in_sizes[0] / (H * W);

    dim3 block(128, 1, 1);
    dim3 grid(W / 64, (H / 32) / 4, B);   // 16 x 8 x B = 1024 CTAs, single wave @8/SM
    bilateral_blur_v11<<<grid, block>>>(bright, dark, depths,
                                        dv, sv, dexp, deps, ce,
                                        out, H, W);
}